// round 1
// baseline (speedup 1.0000x reference)
#include <cuda_runtime.h>
#include <stdint.h>

// Problem constants (max sizes for static scratch)
#define MAXN 50000
#define MAXE 800000
#define XD 32
#define HD 96
#define OD 64

// Scratch (device globals — no allocation allowed)
__device__ float g_A[XD * HD];      // W1[0:32,:] - W1[48:80,:]
__device__ float g_B[XD * HD];      // W1[48:80,:]
__device__ float g_c[HD];           // b1 + scalars @ W1[32:48,:]
__device__ float g_p[MAXN * HD];    // x @ A
__device__ float g_q[MAXN * HD];    // x @ B
__device__ float g_Z[MAXN * HD];    // per-dst relu-sum accumulator
__device__ int   g_deg[MAXN];
__device__ int   g_is64;            // edge_index dtype flag

// --- detect int64 vs int32 edge_index layout ---
__global__ void detect_kernel(const int* __restrict__ ei32) {
    __shared__ int any;
    if (threadIdx.x == 0) any = 0;
    __syncthreads();
    for (int i = threadIdx.x; i < 1024; i += blockDim.x) {
        if (ei32[2 * i + 1] != 0) any = 1;
    }
    __syncthreads();
    if (threadIdx.x == 0) g_is64 = (any == 0) ? 1 : 0;
}

// --- prep: build A, B, c from W1, b1, scalars ---
__global__ void prep_kernel(const float* __restrict__ W1,
                            const float* __restrict__ b1,
                            const float* __restrict__ scalars) {
    int j = threadIdx.x;  // 0..95
    if (j >= HD) return;
    float c = b1[j];
#pragma unroll
    for (int s = 0; s < 16; s++) c += scalars[s] * W1[(32 + s) * HD + j];
    g_c[j] = c;
#pragma unroll
    for (int r = 0; r < XD; r++) {
        float wB = W1[(48 + r) * HD + j];
        g_A[r * HD + j] = W1[r * HD + j] - wB;
        g_B[r * HD + j] = wB;
    }
}

// --- zero Z and deg ---
__global__ void zero_kernel(int n) {
    int total = n * HD;
    for (int i = blockIdx.x * blockDim.x + threadIdx.x; i < total;
         i += gridDim.x * blockDim.x) {
        g_Z[i] = 0.0f;
        if (i < n) g_deg[i] = 0;
    }
}

// --- per-node p, q: 96 threads per block = one node ---
__global__ void pq_kernel(const float* __restrict__ x, int n) {
    int node = blockIdx.x;
    if (node >= n) return;
    int j = threadIdx.x;  // 0..95
    __shared__ float xs[XD];
    if (j < XD) xs[j] = x[node * XD + j];
    __syncthreads();
    float p = 0.f, q = 0.f;
#pragma unroll
    for (int r = 0; r < XD; r++) {
        float xv = xs[r];
        p = fmaf(xv, g_A[r * HD + j], p);
        q = fmaf(xv, g_B[r * HD + j], q);
    }
    g_p[node * HD + j] = p;
    g_q[node * HD + j] = q;
}

// --- edge pass: Z[dst] += relu(p[dst] + q[src] + c); deg[dst]++ ---
// one warp per edge, 8 edges per 256-thread block
__global__ void edge_kernel(const void* __restrict__ ei, int e_count) {
    int e = blockIdx.x * 8 + (threadIdx.x >> 5);
    if (e >= e_count) return;
    int lane = threadIdx.x & 31;

    int src, dst;
    if (g_is64) {
        const long long* p64 = (const long long*)ei;
        src = (int)p64[e];
        dst = (int)p64[e_count + e];
    } else {
        const int* p32 = (const int*)ei;
        src = p32[e];
        dst = p32[e_count + e];
    }

    const float* pp = g_p + (size_t)dst * HD;
    const float* qq = g_q + (size_t)src * HD;
    float* zz = g_Z + (size_t)dst * HD;

#pragma unroll
    for (int t = 0; t < 3; t++) {
        int j = lane + t * 32;
        float v = pp[j] + qq[j] + g_c[j];
        v = fmaxf(v, 0.0f);
        atomicAdd(&zz[j], v);
    }
    if (lane == 0) atomicAdd(&g_deg[dst], 1);
}

// --- output: out[node] = Z[node] @ W2 + deg[node]*b2 ---
// 256 threads = 4 nodes x 64 cols
__global__ void out_kernel(const float* __restrict__ W2,
                           const float* __restrict__ b2,
                           float* __restrict__ out, int n) {
    int col = threadIdx.x & 63;
    int node = blockIdx.x * 4 + (threadIdx.x >> 6);
    if (node >= n) return;
    float acc = (float)g_deg[node] * b2[col];
    const float* z = g_Z + (size_t)node * HD;
#pragma unroll
    for (int k = 0; k < HD; k++) {
        acc = fmaf(__ldg(&z[k]), __ldg(&W2[k * OD + col]), acc);
    }
    out[(size_t)node * OD + col] = acc;
}

extern "C" void kernel_launch(void* const* d_in, const int* in_sizes, int n_in,
                              void* d_out, int out_size) {
    const float* x       = (const float*)d_in[0];
    const float* scalars = (const float*)d_in[1];
    const float* W1      = (const float*)d_in[2];
    const float* b1      = (const float*)d_in[3];
    const float* W2      = (const float*)d_in[4];
    const float* b2      = (const float*)d_in[5];
    const void*  ei      = d_in[6];
    float* out = (float*)d_out;

    int n = in_sizes[0] / XD;       // 50000
    int e = in_sizes[6] / 2;        // 800000

    detect_kernel<<<1, 256>>>((const int*)ei);
    prep_kernel<<<1, HD>>>(W1, b1, scalars);
    zero_kernel<<<(n * HD + 255) / 256, 256>>>(n);
    pq_kernel<<<n, HD>>>(x, n);
    edge_kernel<<<(e + 7) / 8, 256>>>(ei, e);
    out_kernel<<<(n + 3) / 4, 256>>>(W2, b2, out, n);
}

// round 2
// speedup vs baseline: 1.1691x; 1.1691x over previous
#include <cuda_runtime.h>
#include <stdint.h>

#define MAXN 50000
#define MAXE 800000
#define XD 32
#define HD 96
#define OD 64

// ---- device scratch (no allocation allowed) ----
__device__ float g_A[XD * HD];        // W1[0:32,:] - W1[48:80,:]
__device__ float g_B[XD * HD];        // W1[48:80,:]
__device__ float g_c[HD];             // b1 + scalars @ W1[32:48,:]
__device__ float g_p[MAXN * HD];      // x @ A + c   (c folded in)
__device__ float g_q[MAXN * HD];      // x @ B
__device__ int   g_deg[MAXN];
__device__ int   g_off[MAXN + 1];
__device__ int   g_cursor[MAXN];
__device__ int   g_srcs[MAXE];        // src ids sorted by dst
__device__ int   g_is64;

// ---- detect int64 vs int32 edge_index ----
__global__ void detect_kernel(const int* __restrict__ ei32) {
    __shared__ int any;
    if (threadIdx.x == 0) any = 0;
    __syncthreads();
    for (int i = threadIdx.x; i < 1024; i += blockDim.x)
        if (ei32[2 * i + 1] != 0) any = 1;
    __syncthreads();
    if (threadIdx.x == 0) g_is64 = (any == 0) ? 1 : 0;
}

__device__ __forceinline__ int load_idx(const void* ei, int e_count, int i) {
    if (g_is64) return (int)((const long long*)ei)[i];
    return ((const int*)ei)[i];
}

// ---- prep: A, B, c ----
__global__ void prep_kernel(const float* __restrict__ W1,
                            const float* __restrict__ b1,
                            const float* __restrict__ scalars) {
    int j = threadIdx.x;
    if (j >= HD) return;
    float c = b1[j];
#pragma unroll
    for (int s = 0; s < 16; s++) c += scalars[s] * W1[(32 + s) * HD + j];
    g_c[j] = c;
#pragma unroll
    for (int r = 0; r < XD; r++) {
        float wB = W1[(48 + r) * HD + j];
        g_A[r * HD + j] = W1[r * HD + j] - wB;
        g_B[r * HD + j] = wB;
    }
}

// ---- zero deg ----
__global__ void zerodeg_kernel(int n) {
    int i = blockIdx.x * blockDim.x + threadIdx.x;
    if (i < n) g_deg[i] = 0;
}

// ---- histogram of dst ----
__global__ void hist_kernel(const void* __restrict__ ei, int e) {
    int i = blockIdx.x * blockDim.x + threadIdx.x;
    if (i >= e) return;
    int dst = load_idx(ei, e, e + i);
    atomicAdd(&g_deg[dst], 1);
}

// ---- single-block exclusive scan of deg -> off, cursor ----
__global__ void scan_kernel(int n) {
    __shared__ int partial[1024];
    int tid = threadIdx.x;
    int chunk = (n + 1023) / 1024;
    int start = tid * chunk;
    int end = min(start + chunk, n);
    int s = 0;
    for (int i = start; i < end; i++) s += g_deg[i];
    partial[tid] = s;
    __syncthreads();
    // inclusive Hillis-Steele scan
    for (int off = 1; off < 1024; off <<= 1) {
        int v = (tid >= off) ? partial[tid - off] : 0;
        __syncthreads();
        partial[tid] += v;
        __syncthreads();
    }
    int base = (tid == 0) ? 0 : partial[tid - 1];
    for (int i = start; i < end; i++) {
        g_off[i] = base;
        g_cursor[i] = base;
        base += g_deg[i];
    }
    if (tid == 0) g_off[n] = partial[1023];
}

// ---- scatter srcs into dst-sorted order ----
__global__ void scatter_kernel(const void* __restrict__ ei, int e) {
    int i = blockIdx.x * blockDim.x + threadIdx.x;
    if (i >= e) return;
    int src = load_idx(ei, e, i);
    int dst = load_idx(ei, e, e + i);
    int pos = atomicAdd(&g_cursor[dst], 1);
    g_srcs[pos] = src;
}

// ---- per-node p', q with smem-staged weights ----
// 384 threads = 4 groups x 96
__global__ void pq_kernel(const float* __restrict__ x, int n, int iters) {
    __shared__ float sA[XD * HD];
    __shared__ float sB[XD * HD];
    __shared__ float sc[HD];
    __shared__ float xs[4][XD];
    int tid = threadIdx.x;
    for (int i = tid; i < XD * HD; i += 384) { sA[i] = g_A[i]; sB[i] = g_B[i]; }
    if (tid < HD) sc[tid] = g_c[tid];
    __syncthreads();
    int grp = tid / HD;   // 0..3
    int j = tid % HD;     // 0..95
    for (int it = 0; it < iters; ++it) {
        int node = (it * gridDim.x + blockIdx.x) * 4 + grp;
        bool valid = (node < n) && (grp < 4);
        __syncthreads();
        if (valid && j < XD) xs[grp][j] = x[node * XD + j];
        __syncthreads();
        if (valid) {
            float p = sc[j], q = 0.f;
#pragma unroll
            for (int r = 0; r < XD; r++) {
                float xv = xs[grp][r];
                p = fmaf(xv, sA[r * HD + j], p);
                q = fmaf(xv, sB[r * HD + j], q);
            }
            g_p[(size_t)node * HD + j] = p;
            g_q[(size_t)node * HD + j] = q;
        }
    }
}

// ---- fused edge accumulation + output GEMM ----
// 256 threads = 8 warps, one warp per node
__global__ void edgeout_kernel(const float* __restrict__ W2,
                               const float* __restrict__ b2,
                               float* __restrict__ out, int n) {
    __shared__ float sW2[HD * OD];   // 24KB
    __shared__ float sb2[OD];
    __shared__ float zbuf[8][HD];
    int tid = threadIdx.x;
    for (int i = tid; i < HD * OD; i += 256) sW2[i] = W2[i];
    if (tid < OD) sb2[tid] = b2[tid];
    __syncthreads();

    int w = tid >> 5, lane = tid & 31;
    int node = blockIdx.x * 8 + w;
    if (node >= n) return;  // warp-uniform

    int off0 = g_off[node];
    int off1 = g_off[node + 1];
    const float* pp = g_p + (size_t)node * HD;
    float pp0 = pp[lane], pp1 = pp[32 + lane], pp2 = pp[64 + lane];
    float z0 = 0.f, z1 = 0.f, z2 = 0.f;

#pragma unroll 2
    for (int e = off0; e < off1; e++) {
        int src = __ldg(&g_srcs[e]);
        const float* q = g_q + (size_t)src * HD;
        z0 += fmaxf(pp0 + __ldg(&q[lane]), 0.f);
        z1 += fmaxf(pp1 + __ldg(&q[32 + lane]), 0.f);
        z2 += fmaxf(pp2 + __ldg(&q[64 + lane]), 0.f);
    }
    zbuf[w][lane] = z0;
    zbuf[w][32 + lane] = z1;
    zbuf[w][64 + lane] = z2;
    __syncwarp();

    int deg = off1 - off0;
    float a0 = (float)deg * sb2[lane];
    float a1 = (float)deg * sb2[lane + 32];
#pragma unroll
    for (int k = 0; k < HD; k++) {
        float zv = zbuf[w][k];
        a0 = fmaf(zv, sW2[k * OD + lane], a0);
        a1 = fmaf(zv, sW2[k * OD + lane + 32], a1);
    }
    out[(size_t)node * OD + lane] = a0;
    out[(size_t)node * OD + lane + 32] = a1;
}

extern "C" void kernel_launch(void* const* d_in, const int* in_sizes, int n_in,
                              void* d_out, int out_size) {
    const float* x       = (const float*)d_in[0];
    const float* scalars = (const float*)d_in[1];
    const float* W1      = (const float*)d_in[2];
    const float* b1      = (const float*)d_in[3];
    const float* W2      = (const float*)d_in[4];
    const float* b2      = (const float*)d_in[5];
    const void*  ei      = d_in[6];
    float* out = (float*)d_out;

    int n = in_sizes[0] / XD;   // 50000
    int e = in_sizes[6] / 2;    // 800000

    detect_kernel<<<1, 256>>>((const int*)ei);
    prep_kernel<<<1, HD>>>(W1, b1, scalars);
    zerodeg_kernel<<<(n + 255) / 256, 256>>>(n);
    hist_kernel<<<(e + 255) / 256, 256>>>(ei, e);
    scan_kernel<<<1, 1024>>>(n);
    scatter_kernel<<<(e + 255) / 256, 256>>>(ei, e);

    int node_groups = (n + 3) / 4;
    int pq_grid = 1184;  // 8 blocks/SM x 148
    int iters = (node_groups + pq_grid - 1) / pq_grid;
    pq_kernel<<<pq_grid, 384>>>(x, n, iters);

    edgeout_kernel<<<(n + 7) / 8, 256>>>(W2, b2, out, n);
}

// round 3
// speedup vs baseline: 1.7536x; 1.5000x over previous
#include <cuda_runtime.h>
#include <stdint.h>

#define MAXN 50000
#define MAXE 800000
#define XD 32
#define HD 96
#define OD 64
#define NB256 ((MAXN + 255) / 256)

// ---- device scratch ----
__device__ float g_A[XD * HD];
__device__ float g_B[XD * HD];
__device__ float g_c[HD];
__device__ float g_p[MAXN * HD];
__device__ float g_q[MAXN * HD];
__device__ int   g_deg[MAXN];
__device__ int   g_off[MAXN + 1];
__device__ int   g_rank[MAXE];
__device__ int   g_srcs[MAXE];
__device__ int   g_bsum[NB256];
__device__ int   g_bpre[NB256];
__device__ int   g_is64;

__device__ __forceinline__ int load_idx(const void* ei, int i) {
    if (g_is64) return (int)((const long long*)ei)[i];
    return ((const int*)ei)[i];
}

// ---- init: zero deg everywhere; block 0 also does detect + prep ----
__global__ void init_kernel(const float* __restrict__ W1,
                            const float* __restrict__ b1,
                            const float* __restrict__ scalars,
                            const int* __restrict__ ei32, int n) {
    int i = blockIdx.x * blockDim.x + threadIdx.x;
    if (i < n) g_deg[i] = 0;
    if (blockIdx.x == 0) {
        __shared__ int any;
        if (threadIdx.x == 0) any = 0;
        __syncthreads();
        for (int k = threadIdx.x; k < 1024; k += blockDim.x)
            if (ei32[2 * k + 1] != 0) any = 1;
        __syncthreads();
        if (threadIdx.x == 0) g_is64 = (any == 0) ? 1 : 0;
        int j = threadIdx.x;
        if (j < HD) {
            float c = b1[j];
#pragma unroll
            for (int s = 0; s < 16; s++) c += scalars[s] * W1[(32 + s) * HD + j];
            g_c[j] = c;
#pragma unroll
            for (int r = 0; r < XD; r++) {
                float wB = W1[(48 + r) * HD + j];
                g_A[r * HD + j] = W1[r * HD + j] - wB;
                g_B[r * HD + j] = wB;
            }
        }
    }
}

// ---- histogram + rank capture ----
__global__ void hist_kernel(const void* __restrict__ ei, int e) {
    int i = blockIdx.x * blockDim.x + threadIdx.x;
    if (i >= e) return;
    int dst = load_idx(ei, e + i);
    g_rank[i] = atomicAdd(&g_deg[dst], 1);
}

// ---- scan stage 1: per-block sums ----
__global__ void scan1_kernel(int n) {
    __shared__ int sh[256];
    int i = blockIdx.x * 256 + threadIdx.x;
    sh[threadIdx.x] = (i < n) ? g_deg[i] : 0;
    __syncthreads();
    for (int s = 128; s > 0; s >>= 1) {
        if (threadIdx.x < s) sh[threadIdx.x] += sh[threadIdx.x + s];
        __syncthreads();
    }
    if (threadIdx.x == 0) g_bsum[blockIdx.x] = sh[0];
}

// ---- scan stage 2: single-block scan of partials (nb <= 256) ----
__global__ void scan2_kernel(int nb) {
    __shared__ int sh[256];
    int t = threadIdx.x;
    int v = (t < nb) ? g_bsum[t] : 0;
    sh[t] = v;
    __syncthreads();
    for (int off = 1; off < 256; off <<= 1) {
        int add = (t >= off) ? sh[t - off] : 0;
        __syncthreads();
        sh[t] += add;
        __syncthreads();
    }
    if (t < nb) g_bpre[t] = sh[t] - v;   // exclusive
}

// ---- scan stage 3: per-block exclusive rescan -> g_off ----
__global__ void scan3_kernel(int n) {
    __shared__ int sh[256];
    int t = threadIdx.x;
    int i = blockIdx.x * 256 + t;
    int v = (i < n) ? g_deg[i] : 0;
    sh[t] = v;
    __syncthreads();
    for (int off = 1; off < 256; off <<= 1) {
        int add = (t >= off) ? sh[t - off] : 0;
        __syncthreads();
        sh[t] += add;
        __syncthreads();
    }
    if (i < n) {
        int base = g_bpre[blockIdx.x];
        int excl = base + sh[t] - v;
        g_off[i] = excl;
        if (i == n - 1) g_off[n] = excl + v;
    }
}

// ---- deterministic scatter (no atomics) ----
__global__ void scatter_kernel(const void* __restrict__ ei, int e) {
    int i = blockIdx.x * blockDim.x + threadIdx.x;
    if (i >= e) return;
    int src = load_idx(ei, i);
    int dst = load_idx(ei, e + i);
    g_srcs[g_off[dst] + g_rank[i]] = src;
}

// ---- per-node p (with c folded), q: smem-staged weights ----
__global__ void pq_kernel(const float* __restrict__ x, int n, int iters) {
    __shared__ float sA[XD * HD];
    __shared__ float sB[XD * HD];
    __shared__ float sc[HD];
    __shared__ float xs[4][XD];
    int tid = threadIdx.x;
    for (int i = tid; i < XD * HD; i += 384) { sA[i] = g_A[i]; sB[i] = g_B[i]; }
    if (tid < HD) sc[tid] = g_c[tid];
    __syncthreads();
    int grp = tid / HD;
    int j = tid % HD;
    for (int it = 0; it < iters; ++it) {
        int node = (it * gridDim.x + blockIdx.x) * 4 + grp;
        bool valid = (node < n) && (grp < 4);
        __syncthreads();
        if (valid && j < XD) xs[grp][j] = x[node * XD + j];
        __syncthreads();
        if (valid) {
            float p = sc[j], q = 0.f;
#pragma unroll
            for (int r = 0; r < XD; r++) {
                float xv = xs[grp][r];
                p = fmaf(xv, sA[r * HD + j], p);
                q = fmaf(xv, sB[r * HD + j], q);
            }
            g_p[(size_t)node * HD + j] = p;
            g_q[(size_t)node * HD + j] = q;
        }
    }
}

// ---- fused edge accumulation + output GEMM ----
// one warp per node, src ids staged cooperatively, 2-edge manual unroll
__global__ void edgeout_kernel(const float* __restrict__ W2,
                               const float* __restrict__ b2,
                               float* __restrict__ out, int n) {
    __shared__ float sW2[HD * OD];
    __shared__ float sb2[OD];
    __shared__ float zbuf[8][HD];
    int tid = threadIdx.x;
    for (int i = tid; i < HD * OD; i += 256) sW2[i] = W2[i];
    if (tid < OD) sb2[tid] = b2[tid];
    __syncthreads();

    int w = tid >> 5, lane = tid & 31;
    int node = blockIdx.x * 8 + w;
    if (node >= n) return;

    int off0 = g_off[node];
    int off1 = g_off[node + 1];
    const float* pp = g_p + (size_t)node * HD;
    float pp0 = pp[lane], pp1 = pp[32 + lane], pp2 = pp[64 + lane];
    float z0 = 0.f, z1 = 0.f, z2 = 0.f;

    for (int base = off0; base < off1; base += 32) {
        int cnt = min(32, off1 - base);
        int sreg = (lane < cnt) ? __ldg(&g_srcs[base + lane]) : 0;
        int k = 0;
        for (; k + 1 < cnt; k += 2) {
            int s0 = __shfl_sync(0xffffffffu, sreg, k);
            int s1 = __shfl_sync(0xffffffffu, sreg, k + 1);
            const float* q0 = g_q + (size_t)s0 * HD;
            const float* q1 = g_q + (size_t)s1 * HD;
            float a0 = __ldg(&q0[lane]);
            float a1 = __ldg(&q0[32 + lane]);
            float a2 = __ldg(&q0[64 + lane]);
            float c0 = __ldg(&q1[lane]);
            float c1 = __ldg(&q1[32 + lane]);
            float c2 = __ldg(&q1[64 + lane]);
            z0 += fmaxf(pp0 + a0, 0.f) + fmaxf(pp0 + c0, 0.f);
            z1 += fmaxf(pp1 + a1, 0.f) + fmaxf(pp1 + c1, 0.f);
            z2 += fmaxf(pp2 + a2, 0.f) + fmaxf(pp2 + c2, 0.f);
        }
        if (k < cnt) {
            int s0 = __shfl_sync(0xffffffffu, sreg, k);
            const float* q0 = g_q + (size_t)s0 * HD;
            z0 += fmaxf(pp0 + __ldg(&q0[lane]), 0.f);
            z1 += fmaxf(pp1 + __ldg(&q0[32 + lane]), 0.f);
            z2 += fmaxf(pp2 + __ldg(&q0[64 + lane]), 0.f);
        }
    }
    zbuf[w][lane] = z0;
    zbuf[w][32 + lane] = z1;
    zbuf[w][64 + lane] = z2;
    __syncwarp();

    int deg = off1 - off0;
    float a0 = (float)deg * sb2[lane];
    float a1 = (float)deg * sb2[lane + 32];
#pragma unroll
    for (int kk = 0; kk < HD; kk++) {
        float zv = zbuf[w][kk];
        a0 = fmaf(zv, sW2[kk * OD + lane], a0);
        a1 = fmaf(zv, sW2[kk * OD + lane + 32], a1);
    }
    out[(size_t)node * OD + lane] = a0;
    out[(size_t)node * OD + lane + 32] = a1;
}

extern "C" void kernel_launch(void* const* d_in, const int* in_sizes, int n_in,
                              void* d_out, int out_size) {
    const float* x       = (const float*)d_in[0];
    const float* scalars = (const float*)d_in[1];
    const float* W1      = (const float*)d_in[2];
    const float* b1      = (const float*)d_in[3];
    const float* W2      = (const float*)d_in[4];
    const float* b2      = (const float*)d_in[5];
    const void*  ei      = d_in[6];
    float* out = (float*)d_out;

    int n = in_sizes[0] / XD;   // 50000
    int e = in_sizes[6] / 2;    // 800000
    int nb = (n + 255) / 256;

    init_kernel<<<nb, 256>>>(W1, b1, scalars, (const int*)ei, n);
    hist_kernel<<<(e + 255) / 256, 256>>>(ei, e);
    scan1_kernel<<<nb, 256>>>(n);
    scan2_kernel<<<1, 256>>>(nb);
    scan3_kernel<<<nb, 256>>>(n);
    scatter_kernel<<<(e + 255) / 256, 256>>>(ei, e);

    int node_groups = (n + 3) / 4;
    int pq_grid = 1184;
    int iters = (node_groups + pq_grid - 1) / pq_grid;
    pq_kernel<<<pq_grid, 384>>>(x, n, iters);

    edgeout_kernel<<<(n + 7) / 8, 256>>>(W2, b2, out, n);
}

// round 4
// speedup vs baseline: 1.9729x; 1.1251x over previous
#include <cuda_runtime.h>
#include <cuda_fp16.h>
#include <stdint.h>

#define MAXN 50000
#define MAXE 800000
#define XD 32
#define HD 96
#define OD 64
#define NB256 ((MAXN + 255) / 256)

// ---- device scratch ----
__device__ float   g_A[XD * HD];
__device__ float   g_B[XD * HD];
__device__ float   g_c[HD];
__device__ float   g_p[MAXN * HD];        // fp32, c folded in
__device__ __half2 g_qh[MAXN * (HD / 2)]; // q in half2 pairs
__device__ int     g_deg[MAXN];
__device__ int     g_off[MAXN + 1];
__device__ int     g_rank[MAXE];
__device__ int     g_srcs[MAXE];
__device__ int     g_bsum[NB256];
__device__ int     g_is64;

__device__ __forceinline__ int load_idx(const void* ei, int i) {
    if (g_is64) return (int)((const long long*)ei)[i];
    return ((const int*)ei)[i];
}

// ---- init: zero deg; block 0 also detects dtype + builds A/B/c ----
__global__ void init_kernel(const float* __restrict__ W1,
                            const float* __restrict__ b1,
                            const float* __restrict__ scalars,
                            const int* __restrict__ ei32, int n) {
    int i = blockIdx.x * blockDim.x + threadIdx.x;
    if (i < n) g_deg[i] = 0;
    if (blockIdx.x == 0) {
        __shared__ int any;
        if (threadIdx.x == 0) any = 0;
        __syncthreads();
        for (int k = threadIdx.x; k < 1024; k += blockDim.x)
            if (ei32[2 * k + 1] != 0) any = 1;
        __syncthreads();
        if (threadIdx.x == 0) g_is64 = (any == 0) ? 1 : 0;
        int j = threadIdx.x;
        if (j < HD) {
            float c = b1[j];
#pragma unroll
            for (int s = 0; s < 16; s++) c += scalars[s] * W1[(32 + s) * HD + j];
            g_c[j] = c;
#pragma unroll
            for (int r = 0; r < XD; r++) {
                float wB = W1[(48 + r) * HD + j];
                g_A[r * HD + j] = W1[r * HD + j] - wB;
                g_B[r * HD + j] = wB;
            }
        }
    }
}

// ---- fused: pq (blocks [0,pq_blocks)) + hist (rest); independent work ----
__global__ void pqhist_kernel(const float* __restrict__ x,
                              const void* __restrict__ ei,
                              int n, int e, int pq_blocks, int iters) {
    if (blockIdx.x < pq_blocks) {
        __shared__ float sA[XD * HD];
        __shared__ float sB[XD * HD];
        __shared__ float sc[HD];
        __shared__ float xs[8][XD];
        int tid = threadIdx.x;
        for (int i = tid; i < XD * HD; i += 384) { sA[i] = g_A[i]; sB[i] = g_B[i]; }
        if (tid < HD) sc[tid] = g_c[tid];
        __syncthreads();
        int grp = tid / 48;   // 0..7 (node within group-of-8)
        int t = tid % 48;     // output pair index
        for (int it = 0; it < iters; ++it) {
            int node = (it * pq_blocks + (int)blockIdx.x) * 8 + grp;
            __syncthreads();
            if (node < n && t < XD) xs[grp][t] = x[node * XD + t];
            __syncthreads();
            if (node < n) {
                float p0 = sc[2 * t], p1 = sc[2 * t + 1];
                float q0 = 0.f, q1 = 0.f;
#pragma unroll
                for (int r = 0; r < XD; r++) {
                    float xv = xs[grp][r];
                    p0 = fmaf(xv, sA[r * HD + 2 * t], p0);
                    p1 = fmaf(xv, sA[r * HD + 2 * t + 1], p1);
                    q0 = fmaf(xv, sB[r * HD + 2 * t], q0);
                    q1 = fmaf(xv, sB[r * HD + 2 * t + 1], q1);
                }
                ((float2*)g_p)[(size_t)node * 48 + t] = make_float2(p0, p1);
                g_qh[(size_t)node * 48 + t] = __floats2half2_rn(q0, q1);
            }
        }
    } else {
        int i = ((int)blockIdx.x - pq_blocks) * 384 + threadIdx.x;
        if (i < e) {
            int dst = load_idx(ei, e + i);
            g_rank[i] = atomicAdd(&g_deg[dst], 1);
        }
    }
}

__device__ __forceinline__ int warp_reduce(int v) {
#pragma unroll
    for (int o = 16; o > 0; o >>= 1) v += __shfl_down_sync(0xffffffffu, v, o);
    return v;
}

// ---- scanA: per-256-block sums ----
__global__ void scanA_kernel(int n) {
    __shared__ int wsum[8];
    int tid = threadIdx.x;
    int i = blockIdx.x * 256 + tid;
    int v = (i < n) ? g_deg[i] : 0;
    int s = warp_reduce(v);
    if ((tid & 31) == 0) wsum[tid >> 5] = s;
    __syncthreads();
    if (tid < 8) {
        int t = wsum[tid];
#pragma unroll
        for (int o = 4; o > 0; o >>= 1) t += __shfl_down_sync(0xffu, t, o);
        if (tid == 0) g_bsum[blockIdx.x] = t;
    }
}

// ---- scanB: per-block exclusive scan with inline prefix of bsum ----
__global__ void scanB_kernel(int n) {
    __shared__ int warp_pre[8];
    __shared__ int sbase;
    int tid = threadIdx.x;
    int lane = tid & 31, wid = tid >> 5;
    if (tid < 32) {
        int s = 0;
        for (int k = tid; k < (int)blockIdx.x; k += 32) s += g_bsum[k];
        s = warp_reduce(s);
        if (tid == 0) sbase = s;
    }
    int i = blockIdx.x * 256 + tid;
    int v = (i < n) ? g_deg[i] : 0;
    int incl = v;
#pragma unroll
    for (int o = 1; o < 32; o <<= 1) {
        int t = __shfl_up_sync(0xffffffffu, incl, o);
        if (lane >= o) incl += t;
    }
    if (lane == 31) warp_pre[wid] = incl;
    __syncthreads();
    if (tid == 0) {
        int run = 0;
#pragma unroll
        for (int k = 0; k < 8; k++) { int t = warp_pre[k]; warp_pre[k] = run; run += t; }
    }
    __syncthreads();
    if (i < n) {
        int excl = sbase + warp_pre[wid] + incl - v;
        g_off[i] = excl;
        if (i == n - 1) g_off[n] = excl + v;
    }
}

// ---- deterministic scatter ----
__global__ void scatter_kernel(const void* __restrict__ ei, int e) {
    int i = blockIdx.x * blockDim.x + threadIdx.x;
    if (i >= e) return;
    int src = load_idx(ei, i);
    int dst = load_idx(ei, e + i);
    g_srcs[g_off[dst] + g_rank[i]] = src;
}

// ---- fused edge accumulation (fp16 q gathers) + output GEMM ----
__global__ void edgeout_kernel(const float* __restrict__ W2,
                               const float* __restrict__ b2,
                               float* __restrict__ out, int n) {
    __shared__ float sW2[HD * OD];
    __shared__ float sb2[OD];
    __shared__ float zbuf[8][HD];
    int tid = threadIdx.x;
    for (int i = tid; i < HD * OD; i += 256) sW2[i] = W2[i];
    if (tid < OD) sb2[tid] = b2[tid];
    __syncthreads();

    int w = tid >> 5, lane = tid & 31;
    int node = blockIdx.x * 8 + w;
    if (node >= n) return;

    int off0 = g_off[node];
    int off1 = g_off[node + 1];
    const float2* pp2 = (const float2*)g_p + (size_t)node * 48;
    float2 ppa = pp2[lane];                       // dims 2l, 2l+1
    float2 ppb = make_float2(0.f, 0.f);
    if (lane < 16) ppb = pp2[32 + lane];          // dims 64+2l, 65+2l
    float z0x = 0.f, z0y = 0.f, z1x = 0.f, z1y = 0.f;

    for (int base = off0; base < off1; base += 32) {
        int cnt = min(32, off1 - base);
        int sreg = (lane < cnt) ? __ldg(&g_srcs[base + lane]) : 0;
        int k = 0;
        for (; k + 1 < cnt; k += 2) {
            int s0 = __shfl_sync(0xffffffffu, sreg, k);
            int s1 = __shfl_sync(0xffffffffu, sreg, k + 1);
            const __half2* qa = g_qh + (size_t)s0 * 48;
            const __half2* qb = g_qh + (size_t)s1 * 48;
            __half2 a0 = qa[lane];
            __half2 b0 = qb[lane];
            __half2 a1 = __float2half2_rn(0.f), b1 = a1;
            if (lane < 16) { a1 = qa[32 + lane]; b1 = qb[32 + lane]; }
            float2 fa0 = __half22float2(a0), fb0 = __half22float2(b0);
            float2 fa1 = __half22float2(a1), fb1 = __half22float2(b1);
            z0x += fmaxf(ppa.x + fa0.x, 0.f) + fmaxf(ppa.x + fb0.x, 0.f);
            z0y += fmaxf(ppa.y + fa0.y, 0.f) + fmaxf(ppa.y + fb0.y, 0.f);
            if (lane < 16) {
                z1x += fmaxf(ppb.x + fa1.x, 0.f) + fmaxf(ppb.x + fb1.x, 0.f);
                z1y += fmaxf(ppb.y + fa1.y, 0.f) + fmaxf(ppb.y + fb1.y, 0.f);
            }
        }
        if (k < cnt) {
            int s0 = __shfl_sync(0xffffffffu, sreg, k);
            const __half2* qa = g_qh + (size_t)s0 * 48;
            float2 fa0 = __half22float2(qa[lane]);
            z0x += fmaxf(ppa.x + fa0.x, 0.f);
            z0y += fmaxf(ppa.y + fa0.y, 0.f);
            if (lane < 16) {
                float2 fa1 = __half22float2(qa[32 + lane]);
                z1x += fmaxf(ppb.x + fa1.x, 0.f);
                z1y += fmaxf(ppb.y + fa1.y, 0.f);
            }
        }
    }
    zbuf[w][2 * lane] = z0x;
    zbuf[w][2 * lane + 1] = z0y;
    if (lane < 16) {
        zbuf[w][64 + 2 * lane] = z1x;
        zbuf[w][65 + 2 * lane] = z1y;
    }
    __syncwarp();

    int deg = off1 - off0;
    float a0 = (float)deg * sb2[lane];
    float a1 = (float)deg * sb2[lane + 32];
#pragma unroll
    for (int kk = 0; kk < HD; kk++) {
        float zv = zbuf[w][kk];
        a0 = fmaf(zv, sW2[kk * OD + lane], a0);
        a1 = fmaf(zv, sW2[kk * OD + lane + 32], a1);
    }
    out[(size_t)node * OD + lane] = a0;
    out[(size_t)node * OD + lane + 32] = a1;
}

extern "C" void kernel_launch(void* const* d_in, const int* in_sizes, int n_in,
                              void* d_out, int out_size) {
    const float* x       = (const float*)d_in[0];
    const float* scalars = (const float*)d_in[1];
    const float* W1      = (const float*)d_in[2];
    const float* b1      = (const float*)d_in[3];
    const float* W2      = (const float*)d_in[4];
    const float* b2      = (const float*)d_in[5];
    const void*  ei      = d_in[6];
    float* out = (float*)d_out;

    int n = in_sizes[0] / XD;   // 50000
    int e = in_sizes[6] / 2;    // 800000
    int nb = (n + 255) / 256;

    init_kernel<<<nb, 256>>>(W1, b1, scalars, (const int*)ei, n);

    int pq_blocks = 1184;
    int node_groups = (n + 7) / 8;
    int iters = (node_groups + pq_blocks - 1) / pq_blocks;
    int hist_blocks = (e + 383) / 384;
    pqhist_kernel<<<pq_blocks + hist_blocks, 384>>>(x, ei, n, e, pq_blocks, iters);

    scanA_kernel<<<nb, 256>>>(n);
    scanB_kernel<<<nb, 256>>>(n);
    scatter_kernel<<<(e + 255) / 256, 256>>>(ei, e);
    edgeout_kernel<<<(n + 7) / 8, 256>>>(W2, b2, out, n);
}